// round 1
// baseline (speedup 1.0000x reference)
#include <cuda_runtime.h>
#include <cuda_fp16.h>

#define HD 90
#define SD 30
#define VD 16
#define NBINS (HD * SD * VD)
#define HW_SHIFT 20
#define HW (1 << HW_SHIFT)

// Repacked LUT: per (i,j,k) bin, 16 bytes holding both v-corners (k and min(k+1,15)):
//   .x = half2(hue0, hue1), .y = half2(sat0-1, sat1-1), .z = half2(val0-1, val1-1), .w = pad
__device__ uint4 g_lut[NBINS];

__global__ void prep_kernel(const float* __restrict__ lut) {
    int bin = blockIdx.x * blockDim.x + threadIdx.x;
    if (bin >= NBINS) return;
    int k  = bin & (VD - 1);
    int ij = bin >> 4;
    int k1 = min(k + 1, VD - 1);
    const float* e0 = lut + (size_t)bin * 3;
    const float* e1 = lut + (size_t)(ij * VD + k1) * 3;
    __half2 hh = __floats2half2_rn(e0[0],        e1[0]);
    __half2 ss = __floats2half2_rn(e0[1] - 1.0f, e1[1] - 1.0f);
    __half2 vv = __floats2half2_rn(e0[2] - 1.0f, e1[2] - 1.0f);
    uint4 o;
    o.x = *reinterpret_cast<unsigned int*>(&hh);
    o.y = *reinterpret_cast<unsigned int*>(&ss);
    o.z = *reinterpret_cast<unsigned int*>(&vv);
    o.w = 0u;
    g_lut[bin] = o;
}

struct F3 { float x, y, z; };

__device__ __forceinline__ F3 vlerp(uint4 e, float fv) {
    __half2 hh = *reinterpret_cast<const __half2*>(&e.x);
    __half2 sh = *reinterpret_cast<const __half2*>(&e.y);
    __half2 vh = *reinterpret_cast<const __half2*>(&e.z);
    float2 hf = __half22float2(hh);
    float2 sf = __half22float2(sh);
    float2 vf = __half22float2(vh);
    F3 r;
    r.x = hf.x + fv * (hf.y - hf.x);
    r.y = sf.x + fv * (sf.y - sf.x);
    r.z = vf.x + fv * (vf.y - vf.x);
    return r;
}

__device__ __forceinline__ void process_pixel(float r, float g, float b,
                                              float& o0, float& o1, float& o2) {
    const float EPS = 1e-8f;
    r = __saturatef(r); g = __saturatef(g); b = __saturatef(b);

    // ---- rgb2hsv ----
    float cmax  = fmaxf(r, fmaxf(g, b));
    float cmin  = fminf(r, fminf(g, b));
    float delta = cmax - cmin;
    float rd = __frcp_rn(delta + EPS);

    float q = (g - b) * rd;
    q = q - 6.0f * floorf(q * (1.0f / 6.0f));          // floor-mod 6 (matches jnp %)
    float hval = (cmax == r) ? q
               : (cmax == g) ? (b - r) * rd + 2.0f
                             : (r - g) * rd + 4.0f;
    hval *= 60.0f;
    if (delta <= EPS) hval = 0.0f;
    float s = (cmax > EPS) ? delta * __frcp_rn(cmax + EPS) : 0.0f;
    float v = cmax;

    // ---- hsv_lookup (trilinear, v-pair fused in each 16B entry) ----
    float hs  = hval * (HD / 360.0f);
    float h0f = floorf(hs);
    float fh  = hs - h0f;
    int i0 = (int)h0f; if (i0 >= HD) i0 -= HD;
    int i1 = i0 + 1;   if (i1 >= HD) i1 = 0;

    float ssv = fminf(s, 1.0f) * (float)(SD - 1);
    float s0f = floorf(ssv);
    float fs  = ssv - s0f;
    int j0 = (int)s0f;
    int j1 = min(j0 + 1, SD - 1);

    float vsv = v * (float)(VD - 1);
    float v0f = floorf(vsv);
    float fv  = vsv - v0f;
    int k0 = (int)v0f;

    int b00 = (i0 * SD + j0) * VD + k0;
    int b10 = (i1 * SD + j0) * VD + k0;
    int b01 = (i0 * SD + j1) * VD + k0;
    int b11 = (i1 * SD + j1) * VD + k0;

    F3 c00 = vlerp(__ldg(&g_lut[b00]), fv);
    F3 c10 = vlerp(__ldg(&g_lut[b10]), fv);
    F3 c01 = vlerp(__ldg(&g_lut[b01]), fv);
    F3 c11 = vlerp(__ldg(&g_lut[b11]), fv);

    float w00 = (1.0f - fh) * (1.0f - fs);
    float w10 = fh * (1.0f - fs);
    float w01 = (1.0f - fh) * fs;
    float w11 = fh * fs;

    float dh =        w00 * c00.x + w10 * c10.x + w01 * c01.x + w11 * c11.x;
    float sm = 1.0f + w00 * c00.y + w10 * c10.y + w01 * c01.y + w11 * c11.y;
    float vm = 1.0f + w00 * c00.z + w10 * c10.z + w01 * c01.z + w11 * c11.z;

    float h2 = hval + dh;
    h2 = h2 - 360.0f * floorf(h2 * (1.0f / 360.0f));   // floor-mod 360
    float s2 = __saturatef(s * sm);
    float v2 = __saturatef(v * vm);

    // ---- hsv2rgb ----
    float hp  = h2 * (1.0f / 60.0f);
    float cc  = v2 * s2;
    float hpm = hp - 2.0f * floorf(hp * 0.5f);
    float xx  = cc * (1.0f - fabsf(hpm - 1.0f));
    float m   = v2 - cc;
    int sec = (int)floorf(hp);
    if (sec >= 6) sec -= 6;

    float rr = (sec == 0 || sec == 5) ? cc : ((sec == 1 || sec == 4) ? xx : 0.0f);
    float gg = (sec == 1 || sec == 2) ? cc : ((sec == 0 || sec == 3) ? xx : 0.0f);
    float bb = (sec == 3 || sec == 4) ? cc : ((sec == 2 || sec == 5) ? xx : 0.0f);
    rr += m; gg += m; bb += m;

    // ---- einsum RGB2XYZ_D50 + clip ----
    o0 = __saturatef(0.7976749f * rr + 0.1351917f * gg + 0.0313534f  * bb);
    o1 = __saturatef(0.2880402f * rr + 0.7118741f * gg + 8.57e-05f   * bb);
    o2 = __saturatef(0.82521f * bb);
}

__global__ __launch_bounds__(256)
void ProfileLookTableEncoding_kernel(const float* __restrict__ x,
                                     float* __restrict__ out, int npix) {
    int t = blockIdx.x * blockDim.x + threadIdx.x;
    int p = t * 4;
    if (p >= npix) return;
    int bidx = p >> HW_SHIFT;
    int hw   = p & (HW - 1);
    size_t base = (size_t)bidx * 3 * HW + hw;

    float4 R4 = *reinterpret_cast<const float4*>(x + base);
    float4 G4 = *reinterpret_cast<const float4*>(x + base + HW);
    float4 B4 = *reinterpret_cast<const float4*>(x + base + 2 * HW);

    float rr[4] = {R4.x, R4.y, R4.z, R4.w};
    float gg[4] = {G4.x, G4.y, G4.z, G4.w};
    float bb[4] = {B4.x, B4.y, B4.z, B4.w};
    float o0[4], o1[4], o2[4];

#pragma unroll
    for (int u = 0; u < 4; u++) {
        process_pixel(rr[u], gg[u], bb[u], o0[u], o1[u], o2[u]);
    }

    float4 O0 = {o0[0], o0[1], o0[2], o0[3]};
    float4 O1 = {o1[0], o1[1], o1[2], o1[3]};
    float4 O2 = {o2[0], o2[1], o2[2], o2[3]};
    *reinterpret_cast<float4*>(out + base)          = O0;
    *reinterpret_cast<float4*>(out + base + HW)     = O1;
    *reinterpret_cast<float4*>(out + base + 2 * HW) = O2;
}

extern "C" void kernel_launch(void* const* d_in, const int* in_sizes, int n_in,
                              void* d_out, int out_size) {
    const float* x   = (const float*)d_in[0];
    const float* lut = (const float*)d_in[1];
    float* out = (float*)d_out;

    prep_kernel<<<(NBINS + 255) / 256, 256>>>(lut);

    int npix = in_sizes[0] / 3;          // 8 * 1024 * 1024
    int nthreads = npix / 4;
    ProfileLookTableEncoding_kernel<<<nthreads / 256, 256>>>(x, out, npix);
}

// round 2
// speedup vs baseline: 1.1159x; 1.1159x over previous
#include <cuda_runtime.h>
#include <cuda_fp16.h>

#define HD 90
#define SD 30
#define VD 16
#define NBINS (HD * SD * VD)
#define HW_SHIFT 20
#define HW (1 << HW_SHIFT)

// Repacked LUT: per (i,j,k) bin, one 64B-aligned entry holding ALL 8 trilinear
// corners (i0/i1 x j0/j1 x k0/k1):
//   uint4 #0: hue as 4x half2, corners (i0j0),(i0j1),(i1j0),(i1j1), each (k0,k1)
//   uint4 #1: sat-offset-from-1, same layout
//   uint4 #2: val-offset-from-1, same layout
//   uint4 #3: pad (keeps every entry inside a single 128B line)
__device__ uint4 g_lut8[NBINS * 4];

__global__ void prep_kernel(const float* __restrict__ lut) {
    int bin = blockIdx.x * blockDim.x + threadIdx.x;
    if (bin >= NBINS) return;
    int k = bin & (VD - 1);
    int j = (bin / VD) % SD;
    int i = bin / (VD * SD);
    int i1 = (i + 1 == HD) ? 0 : i + 1;
    int j1 = min(j + 1, SD - 1);
    int k1 = min(k + 1, VD - 1);

    // corner (i,j) base float-offsets, order: (i0j0),(i0j1),(i1j0),(i1j1)
    int p[4];
    p[0] = ((i  * SD + j ) * VD + k) * 3;
    p[1] = ((i  * SD + j1) * VD + k) * 3;
    p[2] = ((i1 * SD + j ) * VD + k) * 3;
    p[3] = ((i1 * SD + j1) * VD + k) * 3;
    int dk = (k1 - k) * 3;   // offset from k0 to k1 corner

    uint4 H, S, V;
    unsigned int* Hp = &H.x;
    unsigned int* Sp = &S.x;
    unsigned int* Vp = &V.x;
#pragma unroll
    for (int q = 0; q < 4; q++) {
        const float* e0 = lut + p[q];
        const float* e1 = lut + p[q] + dk;
        __half2 hh = __floats2half2_rn(e0[0],        e1[0]);
        __half2 ss = __floats2half2_rn(e0[1] - 1.0f, e1[1] - 1.0f);
        __half2 vv = __floats2half2_rn(e0[2] - 1.0f, e1[2] - 1.0f);
        Hp[q] = *reinterpret_cast<unsigned int*>(&hh);
        Sp[q] = *reinterpret_cast<unsigned int*>(&ss);
        Vp[q] = *reinterpret_cast<unsigned int*>(&vv);
    }
    g_lut8[bin * 4 + 0] = H;
    g_lut8[bin * 4 + 1] = S;
    g_lut8[bin * 4 + 2] = V;
    // pad word left unwritten; never read
}

// v-lerp one packed half2 corner-pair: lo + fv*(hi - lo)
__device__ __forceinline__ float vl(unsigned int packed, float fv) {
    __half2 h = *reinterpret_cast<const __half2*>(&packed);
    float2 f = __half22float2(h);
    return f.x + fv * (f.y - f.x);
}

__device__ __forceinline__ void process_pixel(float r, float g, float b,
                                              float& o0, float& o1, float& o2) {
    const float EPS = 1e-8f;
    r = __saturatef(r); g = __saturatef(g); b = __saturatef(b);

    // ---- rgb2hsv ----
    float cmax  = fmaxf(r, fmaxf(g, b));
    float cmin  = fminf(r, fminf(g, b));
    float delta = cmax - cmin;
    float rd = __frcp_rn(delta + EPS);

    float q = (g - b) * rd;
    q = q - 6.0f * floorf(q * (1.0f / 6.0f));          // floor-mod 6 (matches jnp %)
    float hval = (cmax == r) ? q
               : (cmax == g) ? (b - r) * rd + 2.0f
                             : (r - g) * rd + 4.0f;
    hval *= 60.0f;
    if (delta <= EPS) hval = 0.0f;
    float s = (cmax > EPS) ? delta * __frcp_rn(cmax + EPS) : 0.0f;
    float v = cmax;

    // ---- hsv_lookup: one packed 48B entry = all 8 corners ----
    float hs  = hval * (HD / 360.0f);
    float h0f = floorf(hs);
    float fh  = hs - h0f;
    int i0 = (int)h0f; if (i0 >= HD) i0 -= HD;

    float ssv = fminf(s, 1.0f) * (float)(SD - 1);
    float s0f = floorf(ssv);
    float fs  = ssv - s0f;
    int j0 = (int)s0f;

    float vsv = v * (float)(VD - 1);
    float v0f = floorf(vsv);
    float fv  = vsv - v0f;
    int k0 = (int)v0f;

    int bin = (i0 * SD + j0) * VD + k0;
    const uint4* e = g_lut8 + (size_t)bin * 4;
    uint4 H = __ldg(e + 0);
    uint4 S = __ldg(e + 1);
    uint4 V = __ldg(e + 2);

    float w00 = (1.0f - fh) * (1.0f - fs);   // (i0,j0)
    float w01 = (1.0f - fh) * fs;            // (i0,j1)
    float w10 = fh * (1.0f - fs);            // (i1,j0)
    float w11 = fh * fs;                     // (i1,j1)

    float dh =        w00 * vl(H.x, fv) + w01 * vl(H.y, fv)
                    + w10 * vl(H.z, fv) + w11 * vl(H.w, fv);
    float sm = 1.0f + w00 * vl(S.x, fv) + w01 * vl(S.y, fv)
                    + w10 * vl(S.z, fv) + w11 * vl(S.w, fv);
    float vm = 1.0f + w00 * vl(V.x, fv) + w01 * vl(V.y, fv)
                    + w10 * vl(V.z, fv) + w11 * vl(V.w, fv);

    float h2 = hval + dh;
    h2 = h2 - 360.0f * floorf(h2 * (1.0f / 360.0f));   // floor-mod 360
    float s2 = __saturatef(s * sm);
    float v2 = __saturatef(v * vm);

    // ---- hsv2rgb ----
    float hp  = h2 * (1.0f / 60.0f);
    float cc  = v2 * s2;
    float hpm = hp - 2.0f * floorf(hp * 0.5f);
    float xx  = cc * (1.0f - fabsf(hpm - 1.0f));
    float m   = v2 - cc;
    int sec = (int)floorf(hp);
    if (sec >= 6) sec -= 6;

    float rr = (sec == 0 || sec == 5) ? cc : ((sec == 1 || sec == 4) ? xx : 0.0f);
    float gg = (sec == 1 || sec == 2) ? cc : ((sec == 0 || sec == 3) ? xx : 0.0f);
    float bb = (sec == 3 || sec == 4) ? cc : ((sec == 2 || sec == 5) ? xx : 0.0f);
    rr += m; gg += m; bb += m;

    // ---- einsum RGB2XYZ_D50 + clip ----
    o0 = __saturatef(0.7976749f * rr + 0.1351917f * gg + 0.0313534f  * bb);
    o1 = __saturatef(0.2880402f * rr + 0.7118741f * gg + 8.57e-05f   * bb);
    o2 = __saturatef(0.82521f * bb);
}

__global__ __launch_bounds__(256)
void ProfileLookTableEncoding_kernel(const float* __restrict__ x,
                                     float* __restrict__ out, int npix) {
    int t = blockIdx.x * blockDim.x + threadIdx.x;
    int p = t * 4;
    if (p >= npix) return;
    int bidx = p >> HW_SHIFT;
    int hw   = p & (HW - 1);
    size_t base = (size_t)bidx * 3 * HW + hw;

    float4 R4 = *reinterpret_cast<const float4*>(x + base);
    float4 G4 = *reinterpret_cast<const float4*>(x + base + HW);
    float4 B4 = *reinterpret_cast<const float4*>(x + base + 2 * HW);

    float rr[4] = {R4.x, R4.y, R4.z, R4.w};
    float gg[4] = {G4.x, G4.y, G4.z, G4.w};
    float bb[4] = {B4.x, B4.y, B4.z, B4.w};
    float o0[4], o1[4], o2[4];

#pragma unroll
    for (int u = 0; u < 4; u++) {
        process_pixel(rr[u], gg[u], bb[u], o0[u], o1[u], o2[u]);
    }

    float4 O0 = {o0[0], o0[1], o0[2], o0[3]};
    float4 O1 = {o1[0], o1[1], o1[2], o1[3]};
    float4 O2 = {o2[0], o2[1], o2[2], o2[3]};
    *reinterpret_cast<float4*>(out + base)          = O0;
    *reinterpret_cast<float4*>(out + base + HW)     = O1;
    *reinterpret_cast<float4*>(out + base + 2 * HW) = O2;
}

extern "C" void kernel_launch(void* const* d_in, const int* in_sizes, int n_in,
                              void* d_out, int out_size) {
    const float* x   = (const float*)d_in[0];
    const float* lut = (const float*)d_in[1];
    float* out = (float*)d_out;

    prep_kernel<<<(NBINS + 255) / 256, 256>>>(lut);

    int npix = in_sizes[0] / 3;          // 8 * 1024 * 1024
    int nthreads = npix / 4;
    ProfileLookTableEncoding_kernel<<<nthreads / 256, 256>>>(x, out, npix);
}

// round 3
// speedup vs baseline: 1.2549x; 1.1245x over previous
#include <cuda_runtime.h>
#include <cuda_fp16.h>

#define HD 90
#define SD 30
#define VD 16
#define NBINS (HD * SD * VD)
#define HW_SHIFT 20
#define HW (1 << HW_SHIFT)

// Hue: per bin, 16B = 8 trilinear hue corners as fp16:
//   4x half2, corners (i0j0),(i0j1),(i1j0),(i1j1), each (k0,k1) pair.
__device__ uint4 g_hue8[NBINS];
// Sat/Val: per bin, 4B = half2(sat_scale-1, val_scale-1). Copied to smem.
__device__ unsigned int g_sv[NBINS];

__global__ void prep_kernel(const float* __restrict__ lut) {
    int bin = blockIdx.x * blockDim.x + threadIdx.x;
    if (bin >= NBINS) return;
    int k = bin & (VD - 1);
    int j = (bin / VD) % SD;
    int i = bin / (VD * SD);
    int i1 = (i + 1 == HD) ? 0 : i + 1;
    int j1 = min(j + 1, SD - 1);
    int k1 = min(k + 1, VD - 1);

    int p[4];
    p[0] = ((i  * SD + j ) * VD + k) * 3;
    p[1] = ((i  * SD + j1) * VD + k) * 3;
    p[2] = ((i1 * SD + j ) * VD + k) * 3;
    p[3] = ((i1 * SD + j1) * VD + k) * 3;
    int dk = (k1 - k) * 3;

    uint4 H;
    unsigned int* Hp = &H.x;
#pragma unroll
    for (int q = 0; q < 4; q++) {
        __half2 hh = __floats2half2_rn(lut[p[q]], lut[p[q] + dk]);
        Hp[q] = *reinterpret_cast<unsigned int*>(&hh);
    }
    g_hue8[bin] = H;

    const float* e = lut + (size_t)bin * 3;
    __half2 sv = __floats2half2_rn(e[1] - 1.0f, e[2] - 1.0f);
    g_sv[bin] = *reinterpret_cast<unsigned int*>(&sv);
}

// v-lerp one packed half2 corner-pair: lo + fv*(hi - lo)
__device__ __forceinline__ float vl(unsigned int packed, float fv) {
    __half2 h = *reinterpret_cast<const __half2*>(&packed);
    float2 f = __half22float2(h);
    return f.x + fv * (f.y - f.x);
}

__device__ __forceinline__ float2 h22f2u(unsigned int u) {
    return __half22float2(*reinterpret_cast<const __half2*>(&u));
}

__device__ __forceinline__ void process_pixel(const unsigned int* __restrict__ s_sv,
                                              float r, float g, float b,
                                              float& o0, float& o1, float& o2) {
    const float EPS = 1e-8f;
    r = __saturatef(r); g = __saturatef(g); b = __saturatef(b);

    // ---- rgb2hsv ----
    float cmax  = fmaxf(r, fmaxf(g, b));
    float cmin  = fminf(r, fminf(g, b));
    float delta = cmax - cmin;
    float rd = __frcp_rn(delta + EPS);

    float q = (g - b) * rd;
    q = q - 6.0f * floorf(q * (1.0f / 6.0f));          // floor-mod 6 (matches jnp %)
    float hval = (cmax == r) ? q
               : (cmax == g) ? (b - r) * rd + 2.0f
                             : (r - g) * rd + 4.0f;
    hval *= 60.0f;
    if (delta <= EPS) hval = 0.0f;
    float s = (cmax > EPS) ? delta * __frcp_rn(cmax + EPS) : 0.0f;
    float v = cmax;

    // ---- lookup indices ----
    float hs  = hval * (HD / 360.0f);
    float h0f = floorf(hs);
    float fh  = hs - h0f;
    int i0 = (int)h0f; if (i0 >= HD) i0 -= HD;

    float ssv = fminf(s, 1.0f) * (float)(SD - 1);
    float s0f = floorf(ssv);
    float fs  = ssv - s0f;
    int j0 = (int)s0f;

    float vsv = v * (float)(VD - 1);
    float v0f = floorf(vsv);
    float fv  = vsv - v0f;
    int k0 = (int)v0f;

    int b00 = (i0 * SD + j0) * VD + k0;
    int di = (i0 == HD - 1) ? -(HD - 1) * SD * VD : SD * VD;
    int dj = (j0 < SD - 1) ? VD : 0;
    int dk = (k0 < VD - 1) ? 1 : 0;   // when k0==15, fv==0 so k1 value has 0 weight

    // ---- hue: one L1 gather of all 8 corners ----
    uint4 H = __ldg(&g_hue8[b00]);

    // ---- sat/val: 8 smem reads (half2 each = sat+val together) ----
    int b01 = b00 + dj;
    int b10 = b00 + di;
    int b11 = b10 + dj;
    float2 f00a = h22f2u(s_sv[b00]);      float2 f00b = h22f2u(s_sv[b00 + dk]);
    float2 f01a = h22f2u(s_sv[b01]);      float2 f01b = h22f2u(s_sv[b01 + dk]);
    float2 f10a = h22f2u(s_sv[b10]);      float2 f10b = h22f2u(s_sv[b10 + dk]);
    float2 f11a = h22f2u(s_sv[b11]);      float2 f11b = h22f2u(s_sv[b11 + dk]);

    float w00 = (1.0f - fh) * (1.0f - fs);
    float w01 = (1.0f - fh) * fs;
    float w10 = fh * (1.0f - fs);
    float w11 = fh * fs;

    float dh = w00 * vl(H.x, fv) + w01 * vl(H.y, fv)
             + w10 * vl(H.z, fv) + w11 * vl(H.w, fv);

    float e00s = f00a.x + fv * (f00b.x - f00a.x);
    float e01s = f01a.x + fv * (f01b.x - f01a.x);
    float e10s = f10a.x + fv * (f10b.x - f10a.x);
    float e11s = f11a.x + fv * (f11b.x - f11a.x);
    float sm = 1.0f + w00 * e00s + w01 * e01s + w10 * e10s + w11 * e11s;

    float e00v = f00a.y + fv * (f00b.y - f00a.y);
    float e01v = f01a.y + fv * (f01b.y - f01a.y);
    float e10v = f10a.y + fv * (f10b.y - f10a.y);
    float e11v = f11a.y + fv * (f11b.y - f11a.y);
    float vm = 1.0f + w00 * e00v + w01 * e01v + w10 * e10v + w11 * e11v;

    float h2 = hval + dh;
    h2 = h2 - 360.0f * floorf(h2 * (1.0f / 360.0f));   // floor-mod 360
    float s2 = __saturatef(s * sm);
    float v2 = __saturatef(v * vm);

    // ---- hsv2rgb ----
    float hp  = h2 * (1.0f / 60.0f);
    float cc  = v2 * s2;
    float hpm = hp - 2.0f * floorf(hp * 0.5f);
    float xx  = cc * (1.0f - fabsf(hpm - 1.0f));
    float m   = v2 - cc;
    int sec = (int)floorf(hp);
    if (sec >= 6) sec -= 6;

    float rr = (sec == 0 || sec == 5) ? cc : ((sec == 1 || sec == 4) ? xx : 0.0f);
    float gg = (sec == 1 || sec == 2) ? cc : ((sec == 0 || sec == 3) ? xx : 0.0f);
    float bb = (sec == 3 || sec == 4) ? cc : ((sec == 2 || sec == 5) ? xx : 0.0f);
    rr += m; gg += m; bb += m;

    // ---- einsum RGB2XYZ_D50 + clip ----
    o0 = __saturatef(0.7976749f * rr + 0.1351917f * gg + 0.0313534f  * bb);
    o1 = __saturatef(0.2880402f * rr + 0.7118741f * gg + 8.57e-05f   * bb);
    o2 = __saturatef(0.82521f * bb);
}

__global__ __launch_bounds__(1024, 1)
void ProfileLookTableEncoding_kernel(const float* __restrict__ x,
                                     float* __restrict__ out, int nquads) {
    extern __shared__ unsigned int s_sv[];

    // Preload sat/val table into smem (173 KB)
    for (int idx = threadIdx.x; idx < NBINS; idx += 1024)
        s_sv[idx] = g_sv[idx];
    __syncthreads();

    int stride = gridDim.x * 1024;
    for (int t = blockIdx.x * 1024 + threadIdx.x; t < nquads; t += stride) {
        int p = t * 4;
        int bidx = p >> HW_SHIFT;
        int hw   = p & (HW - 1);
        size_t base = (size_t)bidx * 3 * HW + hw;

        float4 R4 = *reinterpret_cast<const float4*>(x + base);
        float4 G4 = *reinterpret_cast<const float4*>(x + base + HW);
        float4 B4 = *reinterpret_cast<const float4*>(x + base + 2 * HW);

        float rr[4] = {R4.x, R4.y, R4.z, R4.w};
        float gg[4] = {G4.x, G4.y, G4.z, G4.w};
        float bb[4] = {B4.x, B4.y, B4.z, B4.w};
        float o0[4], o1[4], o2[4];

#pragma unroll
        for (int u = 0; u < 4; u++) {
            process_pixel(s_sv, rr[u], gg[u], bb[u], o0[u], o1[u], o2[u]);
        }

        float4 O0 = {o0[0], o0[1], o0[2], o0[3]};
        float4 O1 = {o1[0], o1[1], o1[2], o1[3]};
        float4 O2 = {o2[0], o2[1], o2[2], o2[3]};
        *reinterpret_cast<float4*>(out + base)          = O0;
        *reinterpret_cast<float4*>(out + base + HW)     = O1;
        *reinterpret_cast<float4*>(out + base + 2 * HW) = O2;
    }
}

extern "C" void kernel_launch(void* const* d_in, const int* in_sizes, int n_in,
                              void* d_out, int out_size) {
    const float* x   = (const float*)d_in[0];
    const float* lut = (const float*)d_in[1];
    float* out = (float*)d_out;

    prep_kernel<<<(NBINS + 255) / 256, 256>>>(lut);

    int dev = 0, nsm = 148;
    cudaGetDevice(&dev);
    cudaDeviceGetAttribute(&nsm, cudaDevAttrMultiProcessorCount, dev);

    const int smem_bytes = NBINS * (int)sizeof(unsigned int);   // 172800 B
    cudaFuncSetAttribute(ProfileLookTableEncoding_kernel,
                         cudaFuncAttributeMaxDynamicSharedMemorySize, smem_bytes);

    int npix = in_sizes[0] / 3;          // 8 * 1024 * 1024
    int nquads = npix / 4;
    ProfileLookTableEncoding_kernel<<<nsm, 1024, smem_bytes>>>(x, out, nquads);
}